// round 9
// baseline (speedup 1.0000x reference)
#include <cuda_runtime.h>
#include <cstddef>

// Grefenstette stack forward, closed-form reformulation.
//
//   s_t[j] = relu(d_j - relu(M_{j,t} - H_j)),  M_{j,t} = max_{j<tau<=t} G_tau
//     G_tau = P_tau - D_{tau-1},  H_j = P_j - D_j,  P = cumsum(u), D = cumsum(d)
//   w_t[j] = min(1, R_t[j]) - min(1, R_t[j+1]),  R = suffix-sum of s_t
//   out[t,b,:] = sum_j w_t[j] * v[j,b,:]
//
// K1: fp64 shuffle-scan prefix sums (block per batch) -> G,H,D [B][T].
// K2: fused weights+gather. Block = 8 consecutive t's of one batch.
//     Warps scan, union their row sets (64-bit window bitmask), the block
//     cooperatively stages distinct v rows in smem once, then warps FMA
//     from smem. Deep/overflow rows use the exact global fallback.

#define TT 512
#define BB 128
#define EE 256

#define FULL 0xFFFFFFFFu
#define GW 8        // warps (= t's) per gather block
#define MAXR 20     // max staged rows (20 KB smem)

__device__ float g_G[BB][TT];
__device__ float g_H[BB][TT];
__device__ float g_D[BB][TT];

// ---------------------------------------------------------------------------
// Kernel 1: fp64 prefix sums (shuffle scan, 2 syncs). One block per batch.
// ---------------------------------------------------------------------------
__global__ __launch_bounds__(TT) void scan_kernel(const float* __restrict__ u,
                                                  const float* __restrict__ d) {
    __shared__ double wsU[16];
    __shared__ double wsD[16];

    const int b    = blockIdx.x;
    const int t    = threadIdx.x;
    const int wid  = t >> 5;
    const int lane = t & 31;

    const float uv = __ldg(&u[t * BB + b]);
    const float dv = __ldg(&d[t * BB + b]);

    double xu = (double)uv;
    double xd = (double)dv;
    #pragma unroll
    for (int o = 1; o < 32; o <<= 1) {
        const double yu = __shfl_up_sync(FULL, xu, o);
        const double yd = __shfl_up_sync(FULL, xd, o);
        if (lane >= o) { xu += yu; xd += yd; }
    }
    if (lane == 31) { wsU[wid] = xu; wsD[wid] = xd; }
    __syncthreads();
    if (wid == 0) {
        double tu = (lane < 16) ? wsU[lane] : 0.0;
        double td = (lane < 16) ? wsD[lane] : 0.0;
        #pragma unroll
        for (int o = 1; o < 16; o <<= 1) {
            const double yu = __shfl_up_sync(FULL, tu, o);
            const double yd = __shfl_up_sync(FULL, td, o);
            if (lane >= o) { tu += yu; td += yd; }
        }
        if (lane < 16) { wsU[lane] = tu; wsD[lane] = td; }
    }
    __syncthreads();
    const double offU = (wid > 0) ? wsU[wid - 1] : 0.0;
    const double offD = (wid > 0) ? wsD[wid - 1] : 0.0;

    const double P  = xu + offU;
    const double Dc = xd + offD;

    g_G[b][t] = (float)(P - (Dc - (double)dv));  // P_t - D_{t-1}
    g_H[b][t] = (float)(P - Dc);                 // P_t - D_t
    g_D[b][t] = dv;
}

// ---------------------------------------------------------------------------
// Kernel 2: fused weights + gather with cooperative smem row staging.
// Grid (TT/GW, BB), 256 threads.
// ---------------------------------------------------------------------------
__global__ __launch_bounds__(GW * 32) void gather_kernel(
    const float* __restrict__ v, float* __restrict__ out) {
    __shared__ unsigned long long uni;   // union of needed window rows
    __shared__ int    slot_of[64];       // window pos -> smem slot (-1 = none)
    __shared__ int    row_p[MAXR];       // smem slot -> window pos
    __shared__ float4 rows[MAXR][EE / 4];

    const int tid  = threadIdx.x;
    const int warp = tid >> 5;
    const int lane = tid & 31;
    const int t0   = blockIdx.x * GW;
    const int t    = t0 + warp;
    const int b    = blockIdx.y;
    const int lo   = (t0 >= 56) ? t0 - 56 : 0;   // window = [lo, t0+8), <=64

    if (tid == 0) uni = 0ULL;
    __syncthreads();

    const float4* __restrict__ v4 = reinterpret_cast<const float4*>(v);
    float4* __restrict__ o4       = reinterpret_cast<float4*>(out);

    // ---- First chunk: warp scan over slots t-31..t ----
    const int  j  = t - lane;
    const bool ok = (j >= 0);

    float m        = ok ? __ldg(&g_G[b][j]) : -1e30f;
    const float Hj = ok ? __ldg(&g_H[b][j]) : 0.f;
    const float Dj = ok ? __ldg(&g_D[b][j]) : 0.f;

    #pragma unroll
    for (int o = 1; o < 32; o <<= 1) {
        const float x = __shfl_up_sync(FULL, m, o);
        if (lane >= o) m = fmaxf(m, x);
    }
    float Me = __shfl_up_sync(FULL, m, 1);
    if (lane == 0) Me = -1e30f;

    const float s = ok ? fmaxf(Dj - fmaxf(Me - Hj, 0.f), 0.f) : 0.f;

    float a = s;
    #pragma unroll
    for (int o = 1; o < 32; o <<= 1) {
        const float x = __shfl_up_sync(FULL, a, o);
        if (lane >= o) a += x;
    }
    const float accExc = a - s;
    const float w0 = fminf(a, 1.f) - fminf(accExc, 1.f);

    const unsigned mask = __ballot_sync(FULL, w0 > 0.f);

    // Publish this warp's row set as window bits: pos p = t - src - lo.
    if (lane == 0 && mask) {
        const int sh = t - lo - 31;
        unsigned long long wb = (unsigned long long)__brev(mask);
        wb = (sh >= 0) ? (wb << sh) : (wb >> (-sh));
        atomicOr(&uni, wb);
    }
    __syncthreads();

    const unsigned long long U = uni;
    if (tid < 64) {
        int sl = -1;
        if ((U >> tid) & 1ULL) {
            const int above = __popcll(U >> (tid + 1));
            if (above < MAXR) { sl = above; row_p[above] = tid; }
        }
        slot_of[tid] = sl;
    }
    __syncthreads();

    // ---- Cooperative staging: distinct rows, independent loads ----
    int nst = __popcll(U);
    if (nst > MAXR) nst = MAXR;
    for (int sl = warp; sl < nst; sl += GW) {
        const int jj = lo + row_p[sl];
        const float4* vp = v4 + ((size_t)jj * BB + b) * (EE / 4);
        rows[sl][lane]      = __ldg(vp + lane);
        rows[sl][lane + 32] = __ldg(vp + lane + 32);
    }
    __syncthreads();

    // ---- FMA from smem (global fallback for overflow slots) ----
    float4 r0 = make_float4(0.f, 0.f, 0.f, 0.f);
    float4 r1 = make_float4(0.f, 0.f, 0.f, 0.f);

    unsigned mm = mask;
    while (mm) {
        const int src = __ffs(mm) - 1;
        mm &= mm - 1;
        const float wj = __shfl_sync(FULL, w0, src);
        const int   jj = t - src;
        const int   sl = slot_of[jj - lo];
        float4 a0, a1;
        if (sl >= 0) {
            a0 = rows[sl][lane];
            a1 = rows[sl][lane + 32];
        } else {
            const float4* vp = v4 + ((size_t)jj * BB + b) * (EE / 4);
            a0 = __ldg(vp + lane);
            a1 = __ldg(vp + lane + 32);
        }
        r0.x = fmaf(wj, a0.x, r0.x);
        r0.y = fmaf(wj, a0.y, r0.y);
        r0.z = fmaf(wj, a0.z, r0.z);
        r0.w = fmaf(wj, a0.w, r0.w);
        r1.x = fmaf(wj, a1.x, r1.x);
        r1.y = fmaf(wj, a1.y, r1.y);
        r1.z = fmaf(wj, a1.z, r1.z);
        r1.w = fmaf(wj, a1.w, r1.w);
    }

    // ---- Rare continuation: deeper chunks (exact global warp-scan loop) ----
    float carryAcc = __shfl_sync(FULL, a, 31);
    if (carryAcc < 1.f && t >= 32) {
        float carryM = __shfl_sync(FULL, m, 31);
        for (int jtop = t - 32; jtop >= 0 && carryAcc < 1.f; jtop -= 32) {
            const int  jc  = jtop - lane;
            const bool okc = (jc >= 0);

            float mc        = okc ? __ldg(&g_G[b][jc]) : -1e30f;
            const float Hjc = okc ? __ldg(&g_H[b][jc]) : 0.f;
            const float Djc = okc ? __ldg(&g_D[b][jc]) : 0.f;

            #pragma unroll
            for (int o = 1; o < 32; o <<= 1) {
                const float x = __shfl_up_sync(FULL, mc, o);
                if (lane >= o) mc = fmaxf(mc, x);
            }
            float Mec = __shfl_up_sync(FULL, mc, 1);
            if (lane == 0) Mec = -1e30f;
            Mec = fmaxf(Mec, carryM);

            const float sc = okc ? fmaxf(Djc - fmaxf(Mec - Hjc, 0.f), 0.f) : 0.f;

            float ac = sc;
            #pragma unroll
            for (int o = 1; o < 32; o <<= 1) {
                const float x = __shfl_up_sync(FULL, ac, o);
                if (lane >= o) ac += x;
            }
            const float accInc = carryAcc + ac;
            const float accEx2 = accInc - sc;
            const float wc = fminf(accInc, 1.f) - fminf(accEx2, 1.f);

            unsigned m2 = __ballot_sync(FULL, wc > 0.f);
            while (m2) {
                const int src = __ffs(m2) - 1;
                m2 &= m2 - 1;
                const float wj = __shfl_sync(FULL, wc, src);
                const int   jj = jtop - src;
                const float4* vp = v4 + ((size_t)jj * BB + b) * (EE / 4);
                const float4 b0 = __ldg(vp + lane);
                const float4 b1 = __ldg(vp + lane + 32);
                r0.x = fmaf(wj, b0.x, r0.x);
                r0.y = fmaf(wj, b0.y, r0.y);
                r0.z = fmaf(wj, b0.z, r0.z);
                r0.w = fmaf(wj, b0.w, r0.w);
                r1.x = fmaf(wj, b1.x, r1.x);
                r1.y = fmaf(wj, b1.y, r1.y);
                r1.z = fmaf(wj, b1.z, r1.z);
                r1.w = fmaf(wj, b1.w, r1.w);
            }

            carryAcc = __shfl_sync(FULL, accInc, 31);
            carryM   = fmaxf(carryM, __shfl_sync(FULL, mc, 31));
        }
    }

    float4* op = o4 + ((size_t)t * BB + b) * (EE / 4);
    op[lane]      = r0;
    op[lane + 32] = r1;
}

extern "C" void kernel_launch(void* const* d_in, const int* in_sizes, int n_in,
                              void* d_out, int out_size) {
    const float* v = (const float*)d_in[0];  // [T,B,E]
    const float* u = (const float*)d_in[1];  // [T,B]
    const float* d = (const float*)d_in[2];  // [T,B]
    float* out     = (float*)d_out;          // [T,B,E]

    scan_kernel<<<BB, TT>>>(u, d);

    dim3 ggrid(TT / GW, BB);
    gather_kernel<<<ggrid, GW * 32>>>(v, out);
}

// round 10
// speedup vs baseline: 1.3919x; 1.3919x over previous
#include <cuda_runtime.h>
#include <cstddef>

// Grefenstette stack forward, closed-form reformulation.
//
//   s_t[j] = relu(d_j - relu(M_{j,t} - H_j)),  M_{j,t} = max_{j<tau<=t} G_tau
//     G_tau = P_tau - D_{tau-1},  H_j = P_j - D_j,  P = cumsum(u), D = cumsum(d)
//   w_t[j] = min(1, R_t[j]) - min(1, R_t[j+1]),  R = suffix-sum of s_t
//   out[t,b,:] = sum_j w_t[j] * v[j,b,:]
//
// K1: fp64 shuffle-scan prefix sums (block per batch) -> G,H,D [B][T].
// K2: fused weights+gather, warp per (t,b), occupancy forced to 7 blocks/SM
//     (latency-bound kernel: more resident warps = more hiding).

#define TT 512
#define BB 128
#define EE 256

#define FULL 0xFFFFFFFFu
#define GW 8      // gather warps per block

__device__ float g_G[BB][TT];
__device__ float g_H[BB][TT];
__device__ float g_D[BB][TT];

// ---------------------------------------------------------------------------
// Kernel 1: fp64 prefix sums (shuffle scan, 2 syncs). One block per batch.
// ---------------------------------------------------------------------------
__global__ __launch_bounds__(TT) void scan_kernel(const float* __restrict__ u,
                                                  const float* __restrict__ d) {
    __shared__ double wsU[16];
    __shared__ double wsD[16];

    const int b    = blockIdx.x;
    const int t    = threadIdx.x;
    const int wid  = t >> 5;
    const int lane = t & 31;

    const float uv = __ldg(&u[t * BB + b]);
    const float dv = __ldg(&d[t * BB + b]);

    double xu = (double)uv;
    double xd = (double)dv;
    #pragma unroll
    for (int o = 1; o < 32; o <<= 1) {
        const double yu = __shfl_up_sync(FULL, xu, o);
        const double yd = __shfl_up_sync(FULL, xd, o);
        if (lane >= o) { xu += yu; xd += yd; }
    }
    if (lane == 31) { wsU[wid] = xu; wsD[wid] = xd; }
    __syncthreads();
    if (wid == 0) {
        double tu = (lane < 16) ? wsU[lane] : 0.0;
        double td = (lane < 16) ? wsD[lane] : 0.0;
        #pragma unroll
        for (int o = 1; o < 16; o <<= 1) {
            const double yu = __shfl_up_sync(FULL, tu, o);
            const double yd = __shfl_up_sync(FULL, td, o);
            if (lane >= o) { tu += yu; td += yd; }
        }
        if (lane < 16) { wsU[lane] = tu; wsD[lane] = td; }
    }
    __syncthreads();
    const double offU = (wid > 0) ? wsU[wid - 1] : 0.0;
    const double offD = (wid > 0) ? wsD[wid - 1] : 0.0;

    const double P  = xu + offU;
    const double Dc = xd + offD;

    g_G[b][t] = (float)(P - (Dc - (double)dv));  // P_t - D_{t-1}
    g_H[b][t] = (float)(P - Dc);                 // P_t - D_t
    g_D[b][t] = dv;
}

// ---------------------------------------------------------------------------
// Kernel 2: fused weights + gather. Warp per (t,b); grid (TT/GW, BB).
// minBlocks=7 forces regs <= 36 -> ~87% occupancy.
// ---------------------------------------------------------------------------
__global__ __launch_bounds__(GW * 32, 7) void gather_kernel(
    const float* __restrict__ v, float* __restrict__ out) {
    const int tid  = threadIdx.x;
    const int warp = tid >> 5;
    const int lane = tid & 31;
    const int t    = blockIdx.x * GW + warp;
    const int b    = blockIdx.y;

    const float4* __restrict__ v4 = reinterpret_cast<const float4*>(v);
    float4* __restrict__ o4       = reinterpret_cast<float4*>(out);

    // ---- First chunk: warp scan over slots t-31..t ----
    const int  j  = t - lane;
    const bool ok = (j >= 0);

    float m        = ok ? __ldg(&g_G[b][j]) : -1e30f;
    const float Hj = ok ? __ldg(&g_H[b][j]) : 0.f;
    const float Dj = ok ? __ldg(&g_D[b][j]) : 0.f;

    // Inclusive forward max-scan of G over lanes (lane 0 = slot t).
    #pragma unroll
    for (int o = 1; o < 32; o <<= 1) {
        const float x = __shfl_up_sync(FULL, m, o);
        if (lane >= o) m = fmaxf(m, x);
    }
    float Me = __shfl_up_sync(FULL, m, 1);
    if (lane == 0) Me = -1e30f;

    const float s = ok ? fmaxf(Dj - fmaxf(Me - Hj, 0.f), 0.f) : 0.f;

    // Inclusive forward sum-scan of s over lanes.
    float a = s;
    #pragma unroll
    for (int o = 1; o < 32; o <<= 1) {
        const float x = __shfl_up_sync(FULL, a, o);
        if (lane >= o) a += x;
    }
    const float accExc = a - s;
    const float w0 = fminf(a, 1.f) - fminf(accExc, 1.f);

    float4 r0 = make_float4(0.f, 0.f, 0.f, 0.f);
    float4 r1 = make_float4(0.f, 0.f, 0.f, 0.f);

    unsigned mask = __ballot_sync(FULL, w0 > 0.f);
    while (mask) {
        const int src = __ffs(mask) - 1;
        mask &= mask - 1;
        const float wj = __shfl_sync(FULL, w0, src);
        const int   jj = t - src;
        const float4* vp = v4 + ((size_t)jj * BB + b) * (EE / 4);
        const float4 a0 = __ldg(vp + lane);
        const float4 a1 = __ldg(vp + lane + 32);
        r0.x = fmaf(wj, a0.x, r0.x);
        r0.y = fmaf(wj, a0.y, r0.y);
        r0.z = fmaf(wj, a0.z, r0.z);
        r0.w = fmaf(wj, a0.w, r0.w);
        r1.x = fmaf(wj, a1.x, r1.x);
        r1.y = fmaf(wj, a1.y, r1.y);
        r1.z = fmaf(wj, a1.z, r1.z);
        r1.w = fmaf(wj, a1.w, r1.w);
    }

    // ---- Rare continuation: deeper chunks (exact warp-scan loop) ----
    float carryAcc = __shfl_sync(FULL, a, 31);
    if (carryAcc < 1.f && t >= 32) {
        float carryM = __shfl_sync(FULL, m, 31);
        for (int jtop = t - 32; jtop >= 0 && carryAcc < 1.f; jtop -= 32) {
            const int  jc  = jtop - lane;
            const bool okc = (jc >= 0);

            float mc        = okc ? __ldg(&g_G[b][jc]) : -1e30f;
            const float Hjc = okc ? __ldg(&g_H[b][jc]) : 0.f;
            const float Djc = okc ? __ldg(&g_D[b][jc]) : 0.f;

            #pragma unroll
            for (int o = 1; o < 32; o <<= 1) {
                const float x = __shfl_up_sync(FULL, mc, o);
                if (lane >= o) mc = fmaxf(mc, x);
            }
            float Mec = __shfl_up_sync(FULL, mc, 1);
            if (lane == 0) Mec = -1e30f;
            Mec = fmaxf(Mec, carryM);

            const float sc = okc ? fmaxf(Djc - fmaxf(Mec - Hjc, 0.f), 0.f) : 0.f;

            float ac = sc;
            #pragma unroll
            for (int o = 1; o < 32; o <<= 1) {
                const float x = __shfl_up_sync(FULL, ac, o);
                if (lane >= o) ac += x;
            }
            const float accInc = carryAcc + ac;
            const float accEx2 = accInc - sc;
            const float wc = fminf(accInc, 1.f) - fminf(accEx2, 1.f);

            unsigned m2 = __ballot_sync(FULL, wc > 0.f);
            while (m2) {
                const int src = __ffs(m2) - 1;
                m2 &= m2 - 1;
                const float wj = __shfl_sync(FULL, wc, src);
                const int   jj = jtop - src;
                const float4* vp = v4 + ((size_t)jj * BB + b) * (EE / 4);
                const float4 b0 = __ldg(vp + lane);
                const float4 b1 = __ldg(vp + lane + 32);
                r0.x = fmaf(wj, b0.x, r0.x);
                r0.y = fmaf(wj, b0.y, r0.y);
                r0.z = fmaf(wj, b0.z, r0.z);
                r0.w = fmaf(wj, b0.w, r0.w);
                r1.x = fmaf(wj, b1.x, r1.x);
                r1.y = fmaf(wj, b1.y, r1.y);
                r1.z = fmaf(wj, b1.z, r1.z);
                r1.w = fmaf(wj, b1.w, r1.w);
            }

            carryAcc = __shfl_sync(FULL, accInc, 31);
            carryM   = fmaxf(carryM, __shfl_sync(FULL, mc, 31));
        }
    }

    float4* op = o4 + ((size_t)t * BB + b) * (EE / 4);
    op[lane]      = r0;
    op[lane + 32] = r1;
}

extern "C" void kernel_launch(void* const* d_in, const int* in_sizes, int n_in,
                              void* d_out, int out_size) {
    const float* v = (const float*)d_in[0];  // [T,B,E]
    const float* u = (const float*)d_in[1];  // [T,B]
    const float* d = (const float*)d_in[2];  // [T,B]
    float* out     = (float*)d_out;          // [T,B,E]

    scan_kernel<<<BB, TT>>>(u, d);

    dim3 ggrid(TT / GW, BB);
    gather_kernel<<<ggrid, GW * 32>>>(v, out);
}